// round 2
// baseline (speedup 1.0000x reference)
#include <cuda_runtime.h>
#include <cuda_bf16.h>
#include <cstdint>

#define MARGIN 0.5f
#define POS_W 1.0f
#define NEG_W 1.0f

#define BLOCKS_PER_BATCH 8
#define R_THREADS 256

// Scratch: per-batch sums (allocations forbidden; use __device__ global)
__device__ float g_batch_sum[4096];

__global__ void zero_sums_kernel(int B) {
    int i = blockIdx.x * blockDim.x + threadIdx.x;
    if (i < B) g_batch_sum[i] = 0.0f;
}

// Each block reduces a contiguous chunk of one batch's N*N floats.
__global__ __launch_bounds__(R_THREADS) void batch_sum_kernel(
    const float* __restrict__ graph, int ne_per_batch /* = N*N */) {
    const int b = blockIdx.x / BLOCKS_PER_BATCH;
    const int chunk = blockIdx.x % BLOCKS_PER_BATCH;
    const int vec_per_batch = ne_per_batch >> 2;               // float4 count
    const int vec_per_chunk = vec_per_batch / BLOCKS_PER_BATCH;

    const float4* __restrict__ base =
        reinterpret_cast<const float4*>(graph) +
        (size_t)b * vec_per_batch + (size_t)chunk * vec_per_chunk;

    float acc = 0.0f;
    for (int i = threadIdx.x; i < vec_per_chunk; i += R_THREADS) {
        float4 v = base[i];
        acc += (v.x + v.y) + (v.z + v.w);
    }

    // warp tree reduce
    #pragma unroll
    for (int off = 16; off > 0; off >>= 1)
        acc += __shfl_xor_sync(0xFFFFFFFFu, acc, off);

    __shared__ float warp_sums[R_THREADS / 32];
    const int lane = threadIdx.x & 31, wid = threadIdx.x >> 5;
    if (lane == 0) warp_sums[wid] = acc;
    __syncthreads();

    if (wid == 0) {
        float s = (lane < R_THREADS / 32) ? warp_sums[lane] : 0.0f;
        #pragma unroll
        for (int off = 4; off > 0; off >>= 1)
            s += __shfl_xor_sync(0xFFFFFFFFu, s, off);
        if (lane == 0) atomicAdd(&g_batch_sum[b], s);
    }
}

// One block: pooled sims -> pairwise hinge losses over upper triangle -> mean.
__global__ __launch_bounds__(256) void pair_loss_kernel(
    const int* __restrict__ labels, float* __restrict__ out,
    int B, float inv_ne) {
    __shared__ float gs[1024];
    __shared__ int lab[1024];

    for (int i = threadIdx.x; i < B; i += blockDim.x) {
        gs[i] = g_batch_sum[i] * inv_ne;
        lab[i] = labels[i];
    }
    __syncthreads();

    float acc = 0.0f;
    // thread t handles rows t, t+256, ... ; inner loop j > i
    for (int i = threadIdx.x; i < B; i += blockDim.x) {
        const float gi = gs[i];
        const int li = lab[i];
        for (int j = i + 1; j < B; ++j) {
            const float sim = gi * gs[j];
            const float pos = fmaxf(MARGIN - sim, 0.0f);
            const float neg = fmaxf(sim - (1.0f - MARGIN), 0.0f);
            acc += (li == lab[j]) ? (POS_W * pos) : (NEG_W * neg);
        }
    }

    #pragma unroll
    for (int off = 16; off > 0; off >>= 1)
        acc += __shfl_xor_sync(0xFFFFFFFFu, acc, off);

    __shared__ float warp_sums[8];
    const int lane = threadIdx.x & 31, wid = threadIdx.x >> 5;
    if (lane == 0) warp_sums[wid] = acc;
    __syncthreads();

    if (wid == 0) {
        float s = (lane < 8) ? warp_sums[lane] : 0.0f;
        #pragma unroll
        for (int off = 4; off > 0; off >>= 1)
            s += __shfl_xor_sync(0xFFFFFFFFu, s, off);
        if (lane == 0) {
            const float num_pairs = 0.5f * (float)B * (float)(B - 1);
            out[0] = s / num_pairs;
        }
    }
}

extern "C" void kernel_launch(void* const* d_in, const int* in_sizes, int n_in,
                              void* d_out, int out_size) {
    const float* graph = (const float*)d_in[0];
    const int* labels = (const int*)d_in[1];
    float* out = (float*)d_out;

    const int total = in_sizes[0];   // B * N * N
    const int B = in_sizes[1];       // 256
    const int ne = total / B;        // N*N = 262144

    zero_sums_kernel<<<(B + 255) / 256, 256>>>(B);
    batch_sum_kernel<<<B * BLOCKS_PER_BATCH, R_THREADS>>>(graph, ne);
    pair_loss_kernel<<<1, 256>>>(labels, out, B, 1.0f / (float)ne);
}